// round 3
// baseline (speedup 1.0000x reference)
#include <cuda_runtime.h>
#include <math.h>
#include <stdint.h>

#define DD    4096
#define NT    256
#define NV4   4          // float4 iterations per thread
#define VPT   16         // values per thread
#define K16   16
#define CAPT  576        // top candidate capacity
#define CAPB  320        // bottom candidate capacity

#define TH_TOP 2.3f
#define TH_BOT 0.02f

__device__ float g_rstd[DD];   // 1/(std+eps)
__device__ float g_nmr[DD];    // -mean * rstd
__device__ float g_scal[8];    // 0:tau 1:beta_up 2:gamma 3:beta_fam 4:inv_norm_e

__device__ __forceinline__ float ftanh_fast(float v) {
    float e = __expf(2.0f * v);
    return 1.0f - __fdividef(2.0f, e + 1.0f);
}

__global__ void prep_kernel(const float* __restrict__ ema_mean,
                            const float* __restrict__ ema_sq,
                            const float* __restrict__ ema_out,
                            const float* __restrict__ p_lt,
                            const float* __restrict__ p_lbu,
                            const float* __restrict__ p_lg,
                            const float* __restrict__ p_lbf) {
    __shared__ float sp[NT / 32];
    int tid = threadIdx.x;
    float acc = 0.0f;
    for (int i = tid; i < DD; i += NT) {
        float m = ema_mean[i];
        float v = fmaxf(ema_sq[i] - m * m, 1e-4f);
        float r = 1.0f / (sqrtf(v) + 1e-5f);
        g_rstd[i] = r;
        g_nmr[i]  = -m * r;
        float e = ema_out[i];
        acc = fmaf(e, e, acc);
    }
    #pragma unroll
    for (int o = 16; o; o >>= 1) acc += __shfl_xor_sync(0xffffffffu, acc, o);
    if ((tid & 31) == 0) sp[tid >> 5] = acc;
    __syncthreads();
    if (tid == 0) {
        float s = 0.0f;
        #pragma unroll
        for (int w = 0; w < NT / 32; w++) s += sp[w];
        g_scal[0] = expf(p_lt[0]);                        // tau
        g_scal[1] = log1pf(expf(p_lbu[0]));               // beta_up
        g_scal[2] = log1pf(expf(p_lg[0]));                // gamma
        g_scal[3] = 1.0f / (1.0f + expf(-p_lbf[0]));      // beta_fam
        g_scal[4] = 1.0f / fmaxf(sqrtf(s), 1e-12f);       // 1/||ema_out||
    }
}

// descending insert into 8-deep sorted list r0..r7
#define INS8_TOP(v) do { float _l=(v), _u;                          \
    _u=fmaxf(r0,_l); _l=fminf(r0,_l); r0=_u;                        \
    _u=fmaxf(r1,_l); _l=fminf(r1,_l); r1=_u;                        \
    _u=fmaxf(r2,_l); _l=fminf(r2,_l); r2=_u;                        \
    _u=fmaxf(r3,_l); _l=fminf(r3,_l); r3=_u;                        \
    _u=fmaxf(r4,_l); _l=fminf(r4,_l); r4=_u;                        \
    _u=fmaxf(r5,_l); _l=fminf(r5,_l); r5=_u;                        \
    _u=fmaxf(r6,_l); _l=fminf(r6,_l); r6=_u;                        \
    r7=fmaxf(r7,_l); } while(0)

#define INS8_BOT(v) do { float _l=(v), _u;                          \
    _u=fminf(r0,_l); _l=fmaxf(r0,_l); r0=_u;                        \
    _u=fminf(r1,_l); _l=fmaxf(r1,_l); r1=_u;                        \
    _u=fminf(r2,_l); _l=fmaxf(r2,_l); r2=_u;                        \
    _u=fminf(r3,_l); _l=fmaxf(r3,_l); r3=_u;                        \
    _u=fminf(r4,_l); _l=fmaxf(r4,_l); r4=_u;                        \
    _u=fminf(r5,_l); _l=fmaxf(r5,_l); r5=_u;                        \
    _u=fminf(r6,_l); _l=fmaxf(r6,_l); r6=_u;                        \
    r7=fminf(r7,_l); } while(0)

__global__ __launch_bounds__(NT, 5)
void gelu_gate_kernel(const float* __restrict__ x,
                      const float* __restrict__ ema_out,
                      float* __restrict__ out) {
    __shared__ float s_tz[CAPT];
    __shared__ int   s_ti[CAPT];
    __shared__ float s_bz[CAPB];    // stores |z|
    __shared__ int   s_bi[CAPB];
    __shared__ int   s_cnt[2];
    __shared__ float s_part[2 * (NT / 32)];
    __shared__ float s_thr[2];      // v16 (top), w16 (bot)

    const int   row = blockIdx.x;
    const int   tid = threadIdx.x;
    const float4* xr = reinterpret_cast<const float4*>(x + (size_t)row * DD);
    const float4* rr = reinterpret_cast<const float4*>(g_rstd);
    const float4* nr = reinterpret_cast<const float4*>(g_nmr);
    const float4* er = reinterpret_cast<const float4*>(ema_out);
    float* orow = out + (size_t)row * DD;
    float4* orow4 = reinterpret_cast<float4*>(orow);

    const float C0 = 2.0f * 0.7978845608028654f;            // for 2u directly? no: keep u
    const float G0 = 0.7978845608028654f;
    const float G1 = 0.044715f * 0.7978845608028654f;
    const float INF = __int_as_float(0x7f800000);
    (void)C0;

    if (tid == 0) { s_cnt[0] = 0; s_cnt[1] = 0; }
    __syncthreads();

    float gbuf[VPT];
    float s2 = 0.f, sd = 0.f;

    #pragma unroll
    for (int i = 0; i < NV4; i++) {
        int idx4 = i * NT + tid;
        float4 xv = xr[idx4];
        float4 rv = rr[idx4];
        float4 nv = nr[idx4];
        float4 ev = er[idx4];
        #pragma unroll
        for (int c = 0; c < 4; c++) {
            float xx = (c==0)?xv.x:(c==1)?xv.y:(c==2)?xv.z:xv.w;
            float rz = (c==0)?rv.x:(c==1)?rv.y:(c==2)?rv.z:rv.w;
            float nm = (c==0)?nv.x:(c==1)?nv.y:(c==2)?nv.z:nv.w;
            float ee = (c==0)?ev.x:(c==1)?ev.y:(c==2)?ev.z:ev.w;
            float zz = fmaf(xx, rz, nm);
            float x2 = xx * xx;
            float u  = xx * fmaf(x2, G1, G0);
            float th = ftanh_fast(u);
            float hx = 0.5f * xx;
            float gg = fmaf(hx, th, hx);
            s2 = fmaf(gg, gg, s2);
            sd = fmaf(gg, ee, sd);
            gbuf[i * 4 + c] = gg;
            float az = fabsf(zz);
            if (az > TH_TOP) {
                int p = atomicAdd(&s_cnt[0], 1);
                if (p < CAPT) { s_tz[p] = zz; s_ti[p] = idx4 * 4 + c; }
            } else if (az < TH_BOT) {
                int p = atomicAdd(&s_cnt[1], 1);
                if (p < CAPB) { s_bz[p] = az; s_bi[p] = idx4 * 4 + c; }
            }
        }
    }

    #pragma unroll
    for (int o = 16; o; o >>= 1) {
        s2 += __shfl_xor_sync(0xffffffffu, s2, o);
        sd += __shfl_xor_sync(0xffffffffu, sd, o);
    }
    if ((tid & 31) == 0) {
        s_part[(tid >> 5) * 2 + 0] = s2;
        s_part[(tid >> 5) * 2 + 1] = sd;
    }
    __syncthreads();   // barrier A: candidates + partials visible

    // ---- rare retry loop (block-uniform); common path: single check, break ----
    {
        float thT = TH_TOP, thB = TH_BOT;
        for (int tries = 0; tries < 12; ++tries) {
            int ct = s_cnt[0], cb = s_cnt[1];
            bool badT = (ct < K16) | (ct > CAPT);
            bool badB = (cb < K16) | (cb > CAPB);
            if (!badT && !badB) break;
            if (badT) thT = (ct < K16) ? thT * 0.5f : thT * 1.4f;
            if (badB) thB = (cb < K16) ? thB * 2.0f : thB * 0.5f;
            __syncthreads();
            if (tid == 0) { if (badT) s_cnt[0] = 0; if (badB) s_cnt[1] = 0; }
            __syncthreads();
            for (int i = 0; i < NV4; i++) {
                int idx4 = i * NT + tid;
                float4 xv = xr[idx4];
                float4 rv = rr[idx4];
                float4 nv = nr[idx4];
                #pragma unroll
                for (int c = 0; c < 4; c++) {
                    float xx = (c==0)?xv.x:(c==1)?xv.y:(c==2)?xv.z:xv.w;
                    float rz = (c==0)?rv.x:(c==1)?rv.y:(c==2)?rv.z:rv.w;
                    float nm = (c==0)?nv.x:(c==1)?nv.y:(c==2)?nv.z:nv.w;
                    float zz = fmaf(xx, rz, nm);
                    float az = fabsf(zz);
                    if (badT && az > thT) {
                        int p = atomicAdd(&s_cnt[0], 1);
                        if (p < CAPT) { s_tz[p] = zz; s_ti[p] = idx4 * 4 + c; }
                    }
                    if (badB && az < thB) {
                        int p = atomicAdd(&s_cnt[1], 1);
                        if (p < CAPB) { s_bz[p] = az; s_bi[p] = idx4 * 4 + c; }
                    }
                }
            }
            __syncthreads();
        }
    }

    // ---- cosine gate (every thread, redundant but cheap) ----
    float a = 0.f, b = 0.f;
    #pragma unroll
    for (int w = 0; w < NT / 32; w++) { a += s_part[2*w]; b += s_part[2*w+1]; }
    float nrm = fmaxf(sqrtf(a), 1e-12f);
    float cs  = fminf(fmaxf(b * g_scal[4] / nrm, -1.0f), 1.0f);
    const float gc = __expf(-g_scal[0] * cs);

    // ---- bulk store: out = g * gc ----
    #pragma unroll
    for (int i = 0; i < NV4; i++) {
        float4 ov;
        ov.x = gbuf[i*4+0] * gc;
        ov.y = gbuf[i*4+1] * gc;
        ov.z = gbuf[i*4+2] * gc;
        ov.w = gbuf[i*4+3] * gc;
        orow4[i * NT + tid] = ov;
    }

    // ---- selection: warp 0 -> 16th largest |z| of top list; warp 1 -> 16th smallest ----
    const int wid = tid >> 5, lane = tid & 31;
    if (wid == 0) {
        int ct = min(s_cnt[0], CAPT);
        float r0=-1.f,r1=-1.f,r2=-1.f,r3=-1.f,r4=-1.f,r5=-1.f,r6=-1.f,r7=-1.f;
        for (int k = lane; k < ct; k += 32) {
            float v = fabsf(s_tz[k]);
            INS8_TOP(v);
        }
        float last = -1.f;
        #pragma unroll
        for (int it = 0; it < K16; it++) {
            float m = r0;
            #pragma unroll
            for (int o = 16; o; o >>= 1) m = fmaxf(m, __shfl_xor_sync(0xffffffffu, m, o));
            last = m;
            if (r0 == m) { r0=r1; r1=r2; r2=r3; r3=r4; r4=r5; r5=r6; r6=r7; r7=-1.f; }
        }
        if (lane == 0) s_thr[0] = last;
    } else if (wid == 1) {
        int cb = min(s_cnt[1], CAPB);
        float r0=INF,r1=INF,r2=INF,r3=INF,r4=INF,r5=INF,r6=INF,r7=INF;
        for (int k = lane; k < cb; k += 32) {
            float v = s_bz[k];
            INS8_BOT(v);
        }
        float last = INF;
        #pragma unroll
        for (int it = 0; it < K16; it++) {
            float m = r0;
            #pragma unroll
            for (int o = 16; o; o >>= 1) m = fminf(m, __shfl_xor_sync(0xffffffffu, m, o));
            last = m;
            if (r0 == m) { r0=r1; r1=r2; r2=r3; r3=r4; r4=r5; r5=r6; r6=r7; r7=INF; }
        }
        if (lane == 0) s_thr[1] = last;
    }
    __syncthreads();   // barrier B: bulk stores + thresholds visible

    // ---- overrides: patch the <=32 gated elements ----
    if (wid == 0) {
        const float v16 = s_thr[0];
        const float bu  = g_scal[1];
        const float gm  = g_scal[2];
        int ct = min(s_cnt[0], CAPT);
        for (int k = lane; k < ct; k += 32) {
            float zz = s_tz[k];
            if (fabsf(zz) >= v16) {
                int idx = s_ti[k];
                float gate = fminf(fmaxf(fmaf(bu, tanhf(gm * zz), 1.0f), 0.1f), 8.0f);
                orow[idx] = orow[idx] * gate;
            }
        }
    } else if (wid == 1) {
        const float w16 = s_thr[1];
        const float bf  = g_scal[3];
        int cb = min(s_cnt[1], CAPB);
        for (int k = lane; k < cb; k += 32) {
            if (s_bz[k] <= w16) {
                int idx = s_bi[k];
                orow[idx] = orow[idx] * bf;
            }
        }
    }
}

extern "C" void kernel_launch(void* const* d_in, const int* in_sizes, int n_in,
                              void* d_out, int out_size) {
    const float* x        = (const float*)d_in[0];
    const float* ema_mean = (const float*)d_in[1];
    const float* ema_sq   = (const float*)d_in[2];
    const float* ema_out  = (const float*)d_in[3];
    const float* lt       = (const float*)d_in[4];
    const float* lbu      = (const float*)d_in[5];
    const float* lg       = (const float*)d_in[6];
    const float* lbf      = (const float*)d_in[7];
    float* out = (float*)d_out;

    int rows = in_sizes[0] / DD;
    if (rows < 1) rows = 1;

    prep_kernel<<<1, NT>>>(ema_mean, ema_sq, ema_out, lt, lbu, lg, lbf);
    gelu_gate_kernel<<<rows, NT>>>(x, ema_out, out);
}

// round 4
// speedup vs baseline: 1.0393x; 1.0393x over previous
#include <cuda_runtime.h>
#include <math.h>
#include <stdint.h>

#define DD    4096
#define NT    256
#define NV4   4          // float4 iterations per thread
#define VPT   16         // values per thread
#define K16   16
#define CAPT  576        // top candidate capacity
#define CAPB  320        // bottom candidate capacity

#define TH_TOP 2.3f
#define TH_BOT 0.02f

__device__ float g_rstd[DD];   // 1/(std+eps)
__device__ float g_nmr[DD];    // -mean * rstd
__device__ float g_scal[8];    // 0:tau 1:beta_up 2:gamma 3:beta_fam 4:inv_norm_e

__global__ void prep_kernel(const float* __restrict__ ema_mean,
                            const float* __restrict__ ema_sq,
                            const float* __restrict__ ema_out,
                            const float* __restrict__ p_lt,
                            const float* __restrict__ p_lbu,
                            const float* __restrict__ p_lg,
                            const float* __restrict__ p_lbf) {
    __shared__ float sp[NT / 32];
    int tid = threadIdx.x;
    float acc = 0.0f;
    for (int i = tid; i < DD; i += NT) {
        float m = ema_mean[i];
        float v = fmaxf(ema_sq[i] - m * m, 1e-4f);
        float r = 1.0f / (sqrtf(v) + 1e-5f);
        g_rstd[i] = r;
        g_nmr[i]  = -m * r;
        float e = ema_out[i];
        acc = fmaf(e, e, acc);
    }
    #pragma unroll
    for (int o = 16; o; o >>= 1) acc += __shfl_xor_sync(0xffffffffu, acc, o);
    if ((tid & 31) == 0) sp[tid >> 5] = acc;
    __syncthreads();
    if (tid == 0) {
        float s = 0.0f;
        #pragma unroll
        for (int w = 0; w < NT / 32; w++) s += sp[w];
        g_scal[0] = expf(p_lt[0]);                        // tau
        g_scal[1] = log1pf(expf(p_lbu[0]));               // beta_up
        g_scal[2] = log1pf(expf(p_lg[0]));                // gamma
        g_scal[3] = 1.0f / (1.0f + expf(-p_lbf[0]));      // beta_fam
        g_scal[4] = 1.0f / fmaxf(sqrtf(s), 1e-12f);       // 1/||ema_out||
    }
}

// descending insert into 8-deep sorted list r0..r7
#define INS8_TOP(v) do { float _l=(v), _u;                          \
    _u=fmaxf(r0,_l); _l=fminf(r0,_l); r0=_u;                        \
    _u=fmaxf(r1,_l); _l=fminf(r1,_l); r1=_u;                        \
    _u=fmaxf(r2,_l); _l=fminf(r2,_l); r2=_u;                        \
    _u=fmaxf(r3,_l); _l=fminf(r3,_l); r3=_u;                        \
    _u=fmaxf(r4,_l); _l=fminf(r4,_l); r4=_u;                        \
    _u=fmaxf(r5,_l); _l=fminf(r5,_l); r5=_u;                        \
    _u=fmaxf(r6,_l); _l=fminf(r6,_l); r6=_u;                        \
    r7=fmaxf(r7,_l); } while(0)

#define INS8_BOT(v) do { float _l=(v), _u;                          \
    _u=fminf(r0,_l); _l=fmaxf(r0,_l); r0=_u;                        \
    _u=fminf(r1,_l); _l=fmaxf(r1,_l); r1=_u;                        \
    _u=fminf(r2,_l); _l=fmaxf(r2,_l); r2=_u;                        \
    _u=fminf(r3,_l); _l=fmaxf(r3,_l); r3=_u;                        \
    _u=fminf(r4,_l); _l=fmaxf(r4,_l); r4=_u;                        \
    _u=fminf(r5,_l); _l=fmaxf(r5,_l); r5=_u;                        \
    _u=fminf(r6,_l); _l=fmaxf(r6,_l); r6=_u;                        \
    r7=fminf(r7,_l); } while(0)

__global__ __launch_bounds__(NT, 5)
void gelu_gate_kernel(const float* __restrict__ x,
                      const float* __restrict__ ema_out,
                      float* __restrict__ out) {
    __shared__ float s_tz[CAPT];
    __shared__ int   s_ti[CAPT];
    __shared__ float s_bz[CAPB];    // stores |z|
    __shared__ int   s_bi[CAPB];
    __shared__ int   s_cnt[2];
    __shared__ float s_part[2 * (NT / 32)];
    __shared__ float s_thr[2];      // v16 (top), w16 (bot)

    const int   row = blockIdx.x;
    const int   tid = threadIdx.x;
    const float* xrow = x + (size_t)row * DD;
    const float4* xr = reinterpret_cast<const float4*>(xrow);
    const float4* rr = reinterpret_cast<const float4*>(g_rstd);
    const float4* nr = reinterpret_cast<const float4*>(g_nmr);
    const float4* er = reinterpret_cast<const float4*>(ema_out);
    float* orow = out + (size_t)row * DD;
    float4* orow4 = reinterpret_cast<float4*>(orow);

    // gelu(x) = x - x/(exp(2u)+1), u = x*(G0 + G1*x^2)
    // exp(2u) = exp2( x * (K0 + K1*x^2) )
    const float K0 = 2.0f * 0.7978845608028654f * 1.4426950408889634f;
    const float K1 = 2.0f * 0.044715f * 0.7978845608028654f * 1.4426950408889634f;
    const float INF = __int_as_float(0x7f800000);

    if (tid == 0) { s_cnt[0] = 0; s_cnt[1] = 0; }
    __syncthreads();

    float gbuf[VPT];
    float s2 = 0.f, sd = 0.f;
    unsigned maskC = 0u;

    #pragma unroll
    for (int i = 0; i < NV4; i++) {
        int idx4 = i * NT + tid;
        float4 xv = xr[idx4];
        float4 rv = rr[idx4];
        float4 nv = nr[idx4];
        float4 ev = er[idx4];
        #pragma unroll
        for (int c = 0; c < 4; c++) {
            float xx = (c==0)?xv.x:(c==1)?xv.y:(c==2)?xv.z:xv.w;
            float rz = (c==0)?rv.x:(c==1)?rv.y:(c==2)?rv.z:rv.w;
            float nm = (c==0)?nv.x:(c==1)?nv.y:(c==2)?nv.z:nv.w;
            float ee = (c==0)?ev.x:(c==1)?ev.y:(c==2)?ev.z:ev.w;
            float zz = fmaf(xx, rz, nm);
            float x2 = xx * xx;
            float a  = xx * fmaf(x2, K1, K0);
            float e  = exp2f(a);                 // MUFU.EX2 via fast path
            float d  = __frcp_rn(e + 1.0f);
            float gg = fmaf(-xx, d, xx);
            s2 = fmaf(gg, gg, s2);
            sd = fmaf(gg, ee, sd);
            gbuf[i * 4 + c] = gg;
            float az = fabsf(zz);
            bool hit = (az > TH_TOP) | (az < TH_BOT);
            maskC |= hit ? (1u << (i * 4 + c)) : 0u;
        }
    }

    #pragma unroll
    for (int o = 16; o; o >>= 1) {
        s2 += __shfl_xor_sync(0xffffffffu, s2, o);
        sd += __shfl_xor_sync(0xffffffffu, sd, o);
    }
    if ((tid & 31) == 0) {
        s_part[(tid >> 5) * 2 + 0] = s2;
        s_part[(tid >> 5) * 2 + 1] = sd;
    }

    // ---- deferred pushes (rare: ~0.5 hits/thread expected) ----
    while (maskC) {
        int j = __ffs(maskC) - 1;
        maskC &= maskC - 1;
        int idx = (( (j >> 2) * NT + tid) << 2) + (j & 3);
        float xx = __ldg(xrow + idx);
        float zz = fmaf(xx, g_rstd[idx], g_nmr[idx]);
        float az = fabsf(zz);
        if (az > TH_TOP) {
            int p = atomicAdd(&s_cnt[0], 1);
            if (p < CAPT) { s_tz[p] = zz; s_ti[p] = idx; }
        } else {
            int p = atomicAdd(&s_cnt[1], 1);
            if (p < CAPB) { s_bz[p] = az; s_bi[p] = idx; }
        }
    }
    __syncthreads();   // barrier A: candidates + partials visible

    // ---- rare retry loop (block-uniform); common path: single check, break ----
    {
        float thT = TH_TOP, thB = TH_BOT;
        for (int tries = 0; tries < 12; ++tries) {
            int ct = s_cnt[0], cb = s_cnt[1];
            bool badT = (ct < K16) | (ct > CAPT);
            bool badB = (cb < K16) | (cb > CAPB);
            if (!badT && !badB) break;
            if (badT) thT = (ct < K16) ? thT * 0.5f : thT * 1.4f;
            if (badB) thB = (cb < K16) ? thB * 2.0f : thB * 0.5f;
            __syncthreads();
            if (tid == 0) { if (badT) s_cnt[0] = 0; if (badB) s_cnt[1] = 0; }
            __syncthreads();
            for (int i = 0; i < NV4; i++) {
                int idx4 = i * NT + tid;
                float4 xv = xr[idx4];
                float4 rv = rr[idx4];
                float4 nv = nr[idx4];
                #pragma unroll
                for (int c = 0; c < 4; c++) {
                    float xx = (c==0)?xv.x:(c==1)?xv.y:(c==2)?xv.z:xv.w;
                    float rz = (c==0)?rv.x:(c==1)?rv.y:(c==2)?rv.z:rv.w;
                    float nm = (c==0)?nv.x:(c==1)?nv.y:(c==2)?nv.z:nv.w;
                    float zz = fmaf(xx, rz, nm);
                    float az = fabsf(zz);
                    if (badT && az > thT) {
                        int p = atomicAdd(&s_cnt[0], 1);
                        if (p < CAPT) { s_tz[p] = zz; s_ti[p] = idx4 * 4 + c; }
                    }
                    if (badB && az < thB) {
                        int p = atomicAdd(&s_cnt[1], 1);
                        if (p < CAPB) { s_bz[p] = az; s_bi[p] = idx4 * 4 + c; }
                    }
                }
            }
            __syncthreads();
        }
    }

    // ---- cosine gate (every thread, redundant but cheap) ----
    float a = 0.f, b = 0.f;
    #pragma unroll
    for (int w = 0; w < NT / 32; w++) { a += s_part[2*w]; b += s_part[2*w+1]; }
    float nrm = fmaxf(sqrtf(a), 1e-12f);
    float cs  = fminf(fmaxf(b * g_scal[4] / nrm, -1.0f), 1.0f);
    const float gc = __expf(-g_scal[0] * cs);

    // ---- bulk store: out = g * gc ----
    #pragma unroll
    for (int i = 0; i < NV4; i++) {
        float4 ov;
        ov.x = gbuf[i*4+0] * gc;
        ov.y = gbuf[i*4+1] * gc;
        ov.z = gbuf[i*4+2] * gc;
        ov.w = gbuf[i*4+3] * gc;
        orow4[i * NT + tid] = ov;
    }

    // ---- selection: warp 0 -> 16th largest |z| of top list; warp 1 -> 16th smallest ----
    const int wid = tid >> 5, lane = tid & 31;
    if (wid == 0) {
        int ct = min(s_cnt[0], CAPT);
        float r0=-1.f,r1=-1.f,r2=-1.f,r3=-1.f,r4=-1.f,r5=-1.f,r6=-1.f,r7=-1.f;
        for (int k = lane; k < ct; k += 32) {
            float v = fabsf(s_tz[k]);
            INS8_TOP(v);
        }
        float last = -1.f;
        #pragma unroll
        for (int it = 0; it < K16; it++) {
            float m = r0;
            #pragma unroll
            for (int o = 16; o; o >>= 1) m = fmaxf(m, __shfl_xor_sync(0xffffffffu, m, o));
            last = m;
            if (r0 == m) { r0=r1; r1=r2; r2=r3; r3=r4; r4=r5; r5=r6; r6=r7; r7=-1.f; }
        }
        if (lane == 0) s_thr[0] = last;
    } else if (wid == 1) {
        int cb = min(s_cnt[1], CAPB);
        float r0=INF,r1=INF,r2=INF,r3=INF,r4=INF,r5=INF,r6=INF,r7=INF;
        for (int k = lane; k < cb; k += 32) {
            float v = s_bz[k];
            INS8_BOT(v);
        }
        float last = INF;
        #pragma unroll
        for (int it = 0; it < K16; it++) {
            float m = r0;
            #pragma unroll
            for (int o = 16; o; o >>= 1) m = fminf(m, __shfl_xor_sync(0xffffffffu, m, o));
            last = m;
            if (r0 == m) { r0=r1; r1=r2; r2=r3; r3=r4; r4=r5; r5=r6; r6=r7; r7=INF; }
        }
        if (lane == 0) s_thr[1] = last;
    }
    __syncthreads();   // barrier B: bulk stores + thresholds visible

    // ---- overrides: patch the <=32 gated elements ----
    if (wid == 0) {
        const float v16 = s_thr[0];
        const float bu  = g_scal[1];
        const float gm  = g_scal[2];
        int ct = min(s_cnt[0], CAPT);
        for (int k = lane; k < ct; k += 32) {
            float zz = s_tz[k];
            if (fabsf(zz) >= v16) {
                int idx = s_ti[k];
                float gate = fminf(fmaxf(fmaf(bu, tanhf(gm * zz), 1.0f), 0.1f), 8.0f);
                orow[idx] = orow[idx] * gate;
            }
        }
    } else if (wid == 1) {
        const float w16 = s_thr[1];
        const float bf  = g_scal[3];
        int cb = min(s_cnt[1], CAPB);
        for (int k = lane; k < cb; k += 32) {
            if (s_bz[k] <= w16) {
                int idx = s_bi[k];
                orow[idx] = orow[idx] * bf;
            }
        }
    }
}

extern "C" void kernel_launch(void* const* d_in, const int* in_sizes, int n_in,
                              void* d_out, int out_size) {
    const float* x        = (const float*)d_in[0];
    const float* ema_mean = (const float*)d_in[1];
    const float* ema_sq   = (const float*)d_in[2];
    const float* ema_out  = (const float*)d_in[3];
    const float* lt       = (const float*)d_in[4];
    const float* lbu      = (const float*)d_in[5];
    const float* lg       = (const float*)d_in[6];
    const float* lbf      = (const float*)d_in[7];
    float* out = (float*)d_out;

    int rows = in_sizes[0] / DD;
    if (rows < 1) rows = 1;

    prep_kernel<<<1, NT>>>(ema_mean, ema_sq, ema_out, lt, lbu, lg, lbf);
    gelu_gate_kernel<<<rows, NT>>>(x, ema_out, out);
}

// round 5
// speedup vs baseline: 1.1410x; 1.0980x over previous
#include <cuda_runtime.h>
#include <math.h>
#include <stdint.h>

#define DD    4096
#define NT    256
#define NV4   4          // float4 iterations per thread
#define K16   16
#define CAPT  576        // top candidate capacity
#define CAPB  320        // bottom candidate capacity

#define TH_TOP 2.3f
#define TH_BOT 0.02f

__device__ float g_rstd[DD];   // 1/(std+eps)
__device__ float g_nmr[DD];    // -mean * rstd
__device__ float g_scal[8];    // 0:tau 1:beta_up 2:gamma 3:beta_fam 4:inv_norm_e

__global__ void prep_kernel(const float* __restrict__ ema_mean,
                            const float* __restrict__ ema_sq,
                            const float* __restrict__ ema_out,
                            const float* __restrict__ p_lt,
                            const float* __restrict__ p_lbu,
                            const float* __restrict__ p_lg,
                            const float* __restrict__ p_lbf) {
    __shared__ float sp[NT / 32];
    int tid = threadIdx.x;
    float acc = 0.0f;
    for (int i = tid; i < DD; i += NT) {
        float m = ema_mean[i];
        float v = fmaxf(ema_sq[i] - m * m, 1e-4f);
        float r = 1.0f / (sqrtf(v) + 1e-5f);
        g_rstd[i] = r;
        g_nmr[i]  = -m * r;
        float e = ema_out[i];
        acc = fmaf(e, e, acc);
    }
    #pragma unroll
    for (int o = 16; o; o >>= 1) acc += __shfl_xor_sync(0xffffffffu, acc, o);
    if ((tid & 31) == 0) sp[tid >> 5] = acc;
    __syncthreads();
    if (tid == 0) {
        float s = 0.0f;
        #pragma unroll
        for (int w = 0; w < NT / 32; w++) s += sp[w];
        g_scal[0] = expf(p_lt[0]);                        // tau
        g_scal[1] = log1pf(expf(p_lbu[0]));               // beta_up
        g_scal[2] = log1pf(expf(p_lg[0]));                // gamma
        g_scal[3] = 1.0f / (1.0f + expf(-p_lbf[0]));      // beta_fam
        g_scal[4] = 1.0f / fmaxf(sqrtf(s), 1e-12f);       // 1/||ema_out||
    }
}

// descending insert into 8-deep sorted list r0..r7
#define INS8_TOP(v) do { float _l=(v), _u;                          \
    _u=fmaxf(r0,_l); _l=fminf(r0,_l); r0=_u;                        \
    _u=fmaxf(r1,_l); _l=fminf(r1,_l); r1=_u;                        \
    _u=fmaxf(r2,_l); _l=fminf(r2,_l); r2=_u;                        \
    _u=fmaxf(r3,_l); _l=fminf(r3,_l); r3=_u;                        \
    _u=fmaxf(r4,_l); _l=fminf(r4,_l); r4=_u;                        \
    _u=fmaxf(r5,_l); _l=fminf(r5,_l); r5=_u;                        \
    _u=fmaxf(r6,_l); _l=fminf(r6,_l); r6=_u;                        \
    r7=fmaxf(r7,_l); } while(0)

#define INS8_BOT(v) do { float _l=(v), _u;                          \
    _u=fminf(r0,_l); _l=fmaxf(r0,_l); r0=_u;                        \
    _u=fminf(r1,_l); _l=fmaxf(r1,_l); r1=_u;                        \
    _u=fminf(r2,_l); _l=fmaxf(r2,_l); r2=_u;                        \
    _u=fminf(r3,_l); _l=fmaxf(r3,_l); r3=_u;                        \
    _u=fminf(r4,_l); _l=fmaxf(r4,_l); r4=_u;                        \
    _u=fminf(r5,_l); _l=fmaxf(r5,_l); r5=_u;                        \
    _u=fminf(r6,_l); _l=fmaxf(r6,_l); r6=_u;                        \
    r7=fminf(r7,_l); } while(0)

__global__ __launch_bounds__(NT, 6)
void gelu_gate_kernel(const float* __restrict__ x,
                      const float* __restrict__ ema_out,
                      float* __restrict__ out) {
    __shared__ float s_g[DD];       // 16KB staged gelu values
    __shared__ float s_tz[CAPT];
    __shared__ int   s_ti[CAPT];
    __shared__ float s_bz[CAPB];    // stores |z|
    __shared__ int   s_bi[CAPB];
    __shared__ int   s_cnt[2];
    __shared__ float s_part[2 * (NT / 32)];
    __shared__ float s_thr[2];

    const int   row = blockIdx.x;
    const int   tid = threadIdx.x;
    const float* xrow = x + (size_t)row * DD;
    const float4* xr = reinterpret_cast<const float4*>(xrow);
    const float4* rr = reinterpret_cast<const float4*>(g_rstd);
    const float4* nr = reinterpret_cast<const float4*>(g_nmr);
    const float4* er = reinterpret_cast<const float4*>(ema_out);
    float4* orow4 = reinterpret_cast<float4*>(out + (size_t)row * DD);
    float4* sg4 = reinterpret_cast<float4*>(s_g);

    // gelu(x) = x - x/(exp2(x*(K0+K1*x^2))+1)
    const float K0 = 2.0f * 0.7978845608028654f * 1.4426950408889634f;
    const float K1 = 2.0f * 0.044715f * 0.7978845608028654f * 1.4426950408889634f;
    const float INF = __int_as_float(0x7f800000);

    if (tid == 0) { s_cnt[0] = 0; s_cnt[1] = 0; }
    __syncthreads();

    float s2 = 0.f, sd = 0.f;
    unsigned maskC = 0u;

    #pragma unroll
    for (int i = 0; i < NV4; i++) {
        int idx4 = i * NT + tid;
        float4 xv = xr[idx4];
        float4 rv = rr[idx4];
        float4 nv = nr[idx4];
        float4 ev = er[idx4];
        float4 gv;
        #pragma unroll
        for (int c = 0; c < 4; c++) {
            float xx = (c==0)?xv.x:(c==1)?xv.y:(c==2)?xv.z:xv.w;
            float rz = (c==0)?rv.x:(c==1)?rv.y:(c==2)?rv.z:rv.w;
            float nm = (c==0)?nv.x:(c==1)?nv.y:(c==2)?nv.z:nv.w;
            float ee = (c==0)?ev.x:(c==1)?ev.y:(c==2)?ev.z:ev.w;
            float zz = fmaf(xx, rz, nm);
            float x2 = xx * xx;
            float a  = xx * fmaf(x2, K1, K0);
            float e  = exp2f(a);
            float d  = __frcp_rn(e + 1.0f);
            float gg = fmaf(-xx, d, xx);
            s2 = fmaf(gg, gg, s2);
            sd = fmaf(gg, ee, sd);
            if (c==0) gv.x=gg; else if (c==1) gv.y=gg; else if (c==2) gv.z=gg; else gv.w=gg;
            float az = fabsf(zz);
            bool hit = (az > TH_TOP) | (az < TH_BOT);
            maskC |= hit ? (1u << (i * 4 + c)) : 0u;
        }
        sg4[idx4] = gv;
    }

    #pragma unroll
    for (int o = 16; o; o >>= 1) {
        s2 += __shfl_xor_sync(0xffffffffu, s2, o);
        sd += __shfl_xor_sync(0xffffffffu, sd, o);
    }
    if ((tid & 31) == 0) {
        s_part[(tid >> 5) * 2 + 0] = s2;
        s_part[(tid >> 5) * 2 + 1] = sd;
    }

    // ---- deferred pushes (rare: ~0.9 hits/thread expected) ----
    while (maskC) {
        int j = __ffs(maskC) - 1;
        maskC &= maskC - 1;
        int idx = (((j >> 2) * NT + tid) << 2) + (j & 3);
        float xx = __ldg(xrow + idx);
        float zz = fmaf(xx, g_rstd[idx], g_nmr[idx]);
        float az = fabsf(zz);
        if (az > TH_TOP) {
            int p = atomicAdd(&s_cnt[0], 1);
            if (p < CAPT) { s_tz[p] = zz; s_ti[p] = idx; }
        } else {
            int p = atomicAdd(&s_cnt[1], 1);
            if (p < CAPB) { s_bz[p] = az; s_bi[p] = idx; }
        }
    }
    __syncthreads();   // barrier A: candidates, partials, s_g visible

    // ---- rare retry loop (block-uniform; normally breaks immediately) ----
    {
        float thT = TH_TOP, thB = TH_BOT;
        for (int tries = 0; tries < 12; ++tries) {
            int ct = s_cnt[0], cb = s_cnt[1];
            bool badT = (ct < K16) | (ct > CAPT);
            bool badB = (cb < K16) | (cb > CAPB);
            if (!badT && !badB) break;
            if (badT) thT = (ct < K16) ? thT * 0.5f : thT * 1.4f;
            if (badB) thB = (cb < K16) ? thB * 2.0f : thB * 0.5f;
            __syncthreads();
            if (tid == 0) { if (badT) s_cnt[0] = 0; if (badB) s_cnt[1] = 0; }
            __syncthreads();
            for (int i = 0; i < NV4; i++) {
                int idx4 = i * NT + tid;
                float4 xv = xr[idx4];
                float4 rv = rr[idx4];
                float4 nv = nr[idx4];
                #pragma unroll
                for (int c = 0; c < 4; c++) {
                    float xx = (c==0)?xv.x:(c==1)?xv.y:(c==2)?xv.z:xv.w;
                    float rz = (c==0)?rv.x:(c==1)?rv.y:(c==2)?rv.z:rv.w;
                    float nm = (c==0)?nv.x:(c==1)?nv.y:(c==2)?nv.z:nv.w;
                    float zz = fmaf(xx, rz, nm);
                    float az = fabsf(zz);
                    if (badT && az > thT) {
                        int p = atomicAdd(&s_cnt[0], 1);
                        if (p < CAPT) { s_tz[p] = zz; s_ti[p] = idx4 * 4 + c; }
                    }
                    if (badB && az < thB) {
                        int p = atomicAdd(&s_cnt[1], 1);
                        if (p < CAPB) { s_bz[p] = az; s_bi[p] = idx4 * 4 + c; }
                    }
                }
            }
            __syncthreads();
        }
    }

    // ---- cosine gate (every thread) ----
    float a = 0.f, b = 0.f;
    #pragma unroll
    for (int w = 0; w < NT / 32; w++) { a += s_part[2*w]; b += s_part[2*w+1]; }
    float nrm = fmaxf(sqrtf(a), 1e-12f);
    float cs  = fminf(fmaxf(b * g_scal[4] / nrm, -1.0f), 1.0f);
    const float gc = __expf(-g_scal[0] * cs);

    // ---- selection + in-smem patch: warp0 top, warp1 bot ----
    const int wid = tid >> 5, lane = tid & 31;
    if (wid == 0) {
        int ct = min(s_cnt[0], CAPT);
        float r0=-1.f,r1=-1.f,r2=-1.f,r3=-1.f,r4=-1.f,r5=-1.f,r6=-1.f,r7=-1.f;
        for (int k = lane; k < ct; k += 32) {
            float v = fabsf(s_tz[k]);
            INS8_TOP(v);
        }
        float last = -1.f;
        #pragma unroll
        for (int it = 0; it < K16; it++) {
            float m = r0;
            #pragma unroll
            for (int o = 16; o; o >>= 1) m = fmaxf(m, __shfl_xor_sync(0xffffffffu, m, o));
            last = m;
            if (r0 == m) { r0=r1; r1=r2; r2=r3; r3=r4; r4=r5; r5=r6; r6=r7; r7=-1.f; }
        }
        const float v16 = last;
        const float bu = g_scal[1];
        const float gm = g_scal[2];
        for (int k = lane; k < ct; k += 32) {
            float zz = s_tz[k];
            if (fabsf(zz) >= v16) {
                float gate = fminf(fmaxf(fmaf(bu, tanhf(gm * zz), 1.0f), 0.1f), 8.0f);
                s_g[s_ti[k]] *= gate;
            }
        }
        (void)s_thr;
    } else if (wid == 1) {
        int cb = min(s_cnt[1], CAPB);
        float r0=INF,r1=INF,r2=INF,r3=INF,r4=INF,r5=INF,r6=INF,r7=INF;
        for (int k = lane; k < cb; k += 32) {
            float v = s_bz[k];
            INS8_BOT(v);
        }
        float last = INF;
        #pragma unroll
        for (int it = 0; it < K16; it++) {
            float m = r0;
            #pragma unroll
            for (int o = 16; o; o >>= 1) m = fminf(m, __shfl_xor_sync(0xffffffffu, m, o));
            last = m;
            if (r0 == m) { r0=r1; r1=r2; r2=r3; r3=r4; r4=r5; r5=r6; r6=r7; r7=INF; }
        }
        const float w16 = last;
        const float bf = g_scal[3];
        for (int k = lane; k < cb; k += 32) {
            if (s_bz[k] <= w16) {
                s_g[s_bi[k]] *= bf;
            }
        }
    }
    __syncthreads();   // barrier B: patched s_g visible

    // ---- bulk store: out = s_g * gc ----
    #pragma unroll
    for (int i = 0; i < NV4; i++) {
        int idx4 = i * NT + tid;
        float4 gv = sg4[idx4];
        float4 ov;
        ov.x = gv.x * gc;
        ov.y = gv.y * gc;
        ov.z = gv.z * gc;
        ov.w = gv.w * gc;
        orow4[idx4] = ov;
    }
}

extern "C" void kernel_launch(void* const* d_in, const int* in_sizes, int n_in,
                              void* d_out, int out_size) {
    const float* x        = (const float*)d_in[0];
    const float* ema_mean = (const float*)d_in[1];
    const float* ema_sq   = (const float*)d_in[2];
    const float* ema_out  = (const float*)d_in[3];
    const float* lt       = (const float*)d_in[4];
    const float* lbu      = (const float*)d_in[5];
    const float* lg       = (const float*)d_in[6];
    const float* lbf      = (const float*)d_in[7];
    float* out = (float*)d_out;

    int rows = in_sizes[0] / DD;
    if (rows < 1) rows = 1;

    prep_kernel<<<1, NT>>>(ema_mean, ema_sq, ema_out, lt, lbu, lg, lbf);
    gelu_gate_kernel<<<rows, NT>>>(x, ema_out, out);
}

// round 6
// speedup vs baseline: 1.2023x; 1.0537x over previous
#include <cuda_runtime.h>
#include <math.h>
#include <stdint.h>

#define DD    4096
#define NT    256
#define NV4   4          // float4 iterations per thread
#define K16   16
#define CAPT  576        // top candidate capacity
#define CAPB  320        // bottom candidate capacity

#define TH_TOP 2.3f
#define TH_BOT 0.02f

__device__ float g_rstd[DD];   // 1/(std+eps)
__device__ float g_nmr[DD];    // -mean * rstd
__device__ float g_scal[8];    // 0:tau 1:beta_up 2:gamma 3:beta_fam 4:inv_norm_e

// ---- packed f32x2 helpers (Blackwell) ----
__device__ __forceinline__ uint64_t pk2(float lo, float hi) {
    uint64_t r; asm("mov.b64 %0, {%1, %2};" : "=l"(r) : "f"(lo), "f"(hi)); return r;
}
__device__ __forceinline__ void upk2(uint64_t v, float& lo, float& hi) {
    asm("mov.b64 {%0, %1}, %2;" : "=f"(lo), "=f"(hi) : "l"(v));
}
#define FMA2(d, a, b, c) asm("fma.rn.f32x2 %0, %1, %2, %3;" : "=l"(d) : "l"(a), "l"(b), "l"(c))
#define MUL2(d, a, b)    asm("mul.rn.f32x2 %0, %1, %2;"     : "=l"(d) : "l"(a), "l"(b))
__device__ __forceinline__ float ex2a(float a) {
    float r; asm("ex2.approx.f32 %0, %1;" : "=f"(r) : "f"(a)); return r;
}
__device__ __forceinline__ float rcpa(float a) {
    float r; asm("rcp.approx.f32 %0, %1;" : "=f"(r) : "f"(a)); return r;
}

__global__ void prep_kernel(const float* __restrict__ ema_mean,
                            const float* __restrict__ ema_sq,
                            const float* __restrict__ ema_out,
                            const float* __restrict__ p_lt,
                            const float* __restrict__ p_lbu,
                            const float* __restrict__ p_lg,
                            const float* __restrict__ p_lbf) {
    __shared__ float sp[NT / 32];
    int tid = threadIdx.x;
    float acc = 0.0f;
    for (int i = tid; i < DD; i += NT) {
        float m = ema_mean[i];
        float v = fmaxf(ema_sq[i] - m * m, 1e-4f);
        float r = 1.0f / (sqrtf(v) + 1e-5f);
        g_rstd[i] = r;
        g_nmr[i]  = -m * r;
        float e = ema_out[i];
        acc = fmaf(e, e, acc);
    }
    #pragma unroll
    for (int o = 16; o; o >>= 1) acc += __shfl_xor_sync(0xffffffffu, acc, o);
    if ((tid & 31) == 0) sp[tid >> 5] = acc;
    __syncthreads();
    if (tid == 0) {
        float s = 0.0f;
        #pragma unroll
        for (int w = 0; w < NT / 32; w++) s += sp[w];
        g_scal[0] = expf(p_lt[0]);                        // tau
        g_scal[1] = log1pf(expf(p_lbu[0]));               // beta_up
        g_scal[2] = log1pf(expf(p_lg[0]));                // gamma
        g_scal[3] = 1.0f / (1.0f + expf(-p_lbf[0]));      // beta_fam
        g_scal[4] = 1.0f / fmaxf(sqrtf(s), 1e-12f);       // 1/||ema_out||
    }
}

// descending insert into 8-deep sorted list r0..r7
#define INS8_TOP(v) do { float _l=(v), _u;                          \
    _u=fmaxf(r0,_l); _l=fminf(r0,_l); r0=_u;                        \
    _u=fmaxf(r1,_l); _l=fminf(r1,_l); r1=_u;                        \
    _u=fmaxf(r2,_l); _l=fminf(r2,_l); r2=_u;                        \
    _u=fmaxf(r3,_l); _l=fminf(r3,_l); r3=_u;                        \
    _u=fmaxf(r4,_l); _l=fminf(r4,_l); r4=_u;                        \
    _u=fmaxf(r5,_l); _l=fminf(r5,_l); r5=_u;                        \
    _u=fmaxf(r6,_l); _l=fminf(r6,_l); r6=_u;                        \
    r7=fmaxf(r7,_l); } while(0)

#define INS8_BOT(v) do { float _l=(v), _u;                          \
    _u=fminf(r0,_l); _l=fmaxf(r0,_l); r0=_u;                        \
    _u=fminf(r1,_l); _l=fmaxf(r1,_l); r1=_u;                        \
    _u=fminf(r2,_l); _l=fmaxf(r2,_l); r2=_u;                        \
    _u=fminf(r3,_l); _l=fmaxf(r3,_l); r3=_u;                        \
    _u=fminf(r4,_l); _l=fmaxf(r4,_l); r4=_u;                        \
    _u=fminf(r5,_l); _l=fmaxf(r5,_l); r5=_u;                        \
    _u=fminf(r6,_l); _l=fmaxf(r6,_l); r6=_u;                        \
    r7=fminf(r7,_l); } while(0)

__global__ __launch_bounds__(NT, 6)
void gelu_gate_kernel(const float* __restrict__ x,
                      const float* __restrict__ ema_out,
                      float* __restrict__ out) {
    __shared__ float s_g[DD];       // 16KB staged gelu values
    __shared__ float s_tz[CAPT];
    __shared__ int   s_ti[CAPT];
    __shared__ float s_bz[CAPB];    // stores |z|
    __shared__ int   s_bi[CAPB];
    __shared__ int   s_cnt[2];
    __shared__ float s_part[2 * (NT / 32)];

    const int   row = blockIdx.x;
    const int   tid = threadIdx.x;
    const float* xrow = x + (size_t)row * DD;
    const float4* xr = reinterpret_cast<const float4*>(xrow);
    const float4* rr = reinterpret_cast<const float4*>(g_rstd);
    const float4* nr = reinterpret_cast<const float4*>(g_nmr);
    const float4* er = reinterpret_cast<const float4*>(ema_out);
    float4* orow4 = reinterpret_cast<float4*>(out + (size_t)row * DD);
    float4* sg4 = reinterpret_cast<float4*>(s_g);

    // gelu(x) = x - x/(exp2(x*(K0+K1*x^2))+1)
    const float K0 = 2.0f * 0.7978845608028654f * 1.4426950408889634f;
    const float K1 = 2.0f * 0.044715f * 0.7978845608028654f * 1.4426950408889634f;
    const float INF = __int_as_float(0x7f800000);

    const uint64_t K0_2 = pk2(K0, K0);
    const uint64_t K1_2 = pk2(K1, K1);
    const uint64_t N1_2 = pk2(-1.0f, -1.0f);

    if (tid == 0) { s_cnt[0] = 0; s_cnt[1] = 0; }
    __syncthreads();

    uint64_t s2a = pk2(0.f, 0.f);
    uint64_t sda = pk2(0.f, 0.f);
    unsigned maskC = 0u;

    #pragma unroll
    for (int i = 0; i < NV4; i++) {
        int idx4 = i * NT + tid;
        float4 xv = xr[idx4];
        float4 rv = rr[idx4];
        float4 nv = nr[idx4];
        float4 ev = er[idx4];
        float4 gv;
        #pragma unroll
        for (int h = 0; h < 2; h++) {
            float XL = h ? xv.z : xv.x, XH = h ? xv.w : xv.y;
            float RL = h ? rv.z : rv.x, RH = h ? rv.w : rv.y;
            float NL = h ? nv.z : nv.x, NH = h ? nv.w : nv.y;
            float EL = h ? ev.z : ev.x, EH = h ? ev.w : ev.y;
            uint64_t x2_ = pk2(XL, XH);
            uint64_t r2_ = pk2(RL, RH);
            uint64_t n2_ = pk2(NL, NH);
            uint64_t e2_ = pk2(EL, EH);
            uint64_t z2_; FMA2(z2_, x2_, r2_, n2_);
            uint64_t xx_; MUL2(xx_, x2_, x2_);
            uint64_t t_;  FMA2(t_, xx_, K1_2, K0_2);
            uint64_t a_;  MUL2(a_, x2_, t_);
            float alo, ahi; upk2(a_, alo, ahi);
            uint64_t ee_ = pk2(ex2a(alo), ex2a(ahi));
            uint64_t ep_; FMA2(ep_, ee_, N1_2, N1_2);      // -(e+1)
            float plo, phi; upk2(ep_, plo, phi);
            uint64_t d2_ = pk2(rcpa(plo), rcpa(phi));      // -1/(e+1)
            uint64_t g2_; FMA2(g2_, x2_, d2_, x2_);        // x - x/(e+1)
            FMA2(s2a, g2_, g2_, s2a);
            FMA2(sda, g2_, e2_, sda);
            float zlo, zhi; upk2(z2_, zlo, zhi);
            float glo, ghi; upk2(g2_, glo, ghi);
            if (h == 0) { gv.x = glo; gv.y = ghi; } else { gv.z = glo; gv.w = ghi; }
            int j0 = i * 4 + h * 2;
            maskC |= ((fabsf(zlo) > TH_TOP) | (fabsf(zlo) < TH_BOT)) ? (1u << j0) : 0u;
            maskC |= ((fabsf(zhi) > TH_TOP) | (fabsf(zhi) < TH_BOT)) ? (2u << j0) : 0u;
        }
        sg4[idx4] = gv;
    }

    float s2lo, s2hi, sdlo, sdhi;
    upk2(s2a, s2lo, s2hi);
    upk2(sda, sdlo, sdhi);
    float s2 = s2lo + s2hi;
    float sd = sdlo + sdhi;
    #pragma unroll
    for (int o = 16; o; o >>= 1) {
        s2 += __shfl_xor_sync(0xffffffffu, s2, o);
        sd += __shfl_xor_sync(0xffffffffu, sd, o);
    }
    if ((tid & 31) == 0) {
        s_part[(tid >> 5) * 2 + 0] = s2;
        s_part[(tid >> 5) * 2 + 1] = sd;
    }

    // ---- deferred pushes (rare: ~0.9 hits/thread expected) ----
    while (maskC) {
        int j = __ffs(maskC) - 1;
        maskC &= maskC - 1;
        int idx = (((j >> 2) * NT + tid) << 2) + (j & 3);
        float xx = __ldg(xrow + idx);
        float zz = fmaf(xx, g_rstd[idx], g_nmr[idx]);
        float az = fabsf(zz);
        if (az > TH_TOP) {
            int p = atomicAdd(&s_cnt[0], 1);
            if (p < CAPT) { s_tz[p] = zz; s_ti[p] = idx; }
        } else {
            int p = atomicAdd(&s_cnt[1], 1);
            if (p < CAPB) { s_bz[p] = az; s_bi[p] = idx; }
        }
    }
    __syncthreads();   // barrier A: candidates, partials, s_g visible

    // ---- rare retry loop (block-uniform; normally breaks immediately) ----
    {
        float thT = TH_TOP, thB = TH_BOT;
        for (int tries = 0; tries < 12; ++tries) {
            int ct = s_cnt[0], cb = s_cnt[1];
            bool badT = (ct < K16) | (ct > CAPT);
            bool badB = (cb < K16) | (cb > CAPB);
            if (!badT && !badB) break;
            if (badT) thT = (ct < K16) ? thT * 0.5f : thT * 1.4f;
            if (badB) thB = (cb < K16) ? thB * 2.0f : thB * 0.5f;
            __syncthreads();
            if (tid == 0) { if (badT) s_cnt[0] = 0; if (badB) s_cnt[1] = 0; }
            __syncthreads();
            for (int i = 0; i < NV4; i++) {
                int idx4 = i * NT + tid;
                float4 xv = xr[idx4];
                float4 rv = rr[idx4];
                float4 nv = nr[idx4];
                #pragma unroll
                for (int c = 0; c < 4; c++) {
                    float xx = (c==0)?xv.x:(c==1)?xv.y:(c==2)?xv.z:xv.w;
                    float rz = (c==0)?rv.x:(c==1)?rv.y:(c==2)?rv.z:rv.w;
                    float nm = (c==0)?nv.x:(c==1)?nv.y:(c==2)?nv.z:nv.w;
                    float zz = fmaf(xx, rz, nm);
                    float az = fabsf(zz);
                    if (badT && az > thT) {
                        int p = atomicAdd(&s_cnt[0], 1);
                        if (p < CAPT) { s_tz[p] = zz; s_ti[p] = idx4 * 4 + c; }
                    }
                    if (badB && az < thB) {
                        int p = atomicAdd(&s_cnt[1], 1);
                        if (p < CAPB) { s_bz[p] = az; s_bi[p] = idx4 * 4 + c; }
                    }
                }
            }
            __syncthreads();
        }
    }

    // ---- cosine gate (every thread) ----
    float a = 0.f, b = 0.f;
    #pragma unroll
    for (int w = 0; w < NT / 32; w++) { a += s_part[2*w]; b += s_part[2*w+1]; }
    float nrm = fmaxf(sqrtf(a), 1e-12f);
    float cs  = fminf(fmaxf(b * g_scal[4] / nrm, -1.0f), 1.0f);
    const float gc = __expf(-g_scal[0] * cs);

    // ---- selection + in-smem patch: warp0 top, warp1 bot ----
    const int wid = tid >> 5, lane = tid & 31;
    if (wid == 0) {
        int ct = min(s_cnt[0], CAPT);
        float r0=-1.f,r1=-1.f,r2=-1.f,r3=-1.f,r4=-1.f,r5=-1.f,r6=-1.f,r7=-1.f;
        for (int k = lane; k < ct; k += 32) {
            float v = fabsf(s_tz[k]);
            INS8_TOP(v);
        }
        float last = -1.f;
        #pragma unroll
        for (int it = 0; it < K16; it++) {
            float m = r0;
            #pragma unroll
            for (int o = 16; o; o >>= 1) m = fmaxf(m, __shfl_xor_sync(0xffffffffu, m, o));
            last = m;
            if (r0 == m) { r0=r1; r1=r2; r2=r3; r3=r4; r4=r5; r5=r6; r6=r7; r7=-1.f; }
        }
        const float v16 = last;
        const float bu = g_scal[1];
        const float gm = g_scal[2];
        for (int k = lane; k < ct; k += 32) {
            float zz = s_tz[k];
            if (fabsf(zz) >= v16) {
                float gate = fminf(fmaxf(fmaf(bu, tanhf(gm * zz), 1.0f), 0.1f), 8.0f);
                s_g[s_ti[k]] *= gate;
            }
        }
    } else if (wid == 1) {
        int cb = min(s_cnt[1], CAPB);
        float r0=INF,r1=INF,r2=INF,r3=INF,r4=INF,r5=INF,r6=INF,r7=INF;
        for (int k = lane; k < cb; k += 32) {
            float v = s_bz[k];
            INS8_BOT(v);
        }
        float last = INF;
        #pragma unroll
        for (int it = 0; it < K16; it++) {
            float m = r0;
            #pragma unroll
            for (int o = 16; o; o >>= 1) m = fminf(m, __shfl_xor_sync(0xffffffffu, m, o));
            last = m;
            if (r0 == m) { r0=r1; r1=r2; r2=r3; r3=r4; r4=r5; r5=r6; r6=r7; r7=INF; }
        }
        const float w16 = last;
        const float bf = g_scal[3];
        for (int k = lane; k < cb; k += 32) {
            if (s_bz[k] <= w16) {
                s_g[s_bi[k]] *= bf;
            }
        }
    }
    __syncthreads();   // barrier B: patched s_g visible

    // ---- bulk store: out = s_g * gc ----
    #pragma unroll
    for (int i = 0; i < NV4; i++) {
        int idx4 = i * NT + tid;
        float4 gv = sg4[idx4];
        float4 ov;
        ov.x = gv.x * gc;
        ov.y = gv.y * gc;
        ov.z = gv.z * gc;
        ov.w = gv.w * gc;
        orow4[idx4] = ov;
    }
}

extern "C" void kernel_launch(void* const* d_in, const int* in_sizes, int n_in,
                              void* d_out, int out_size) {
    const float* x        = (const float*)d_in[0];
    const float* ema_mean = (const float*)d_in[1];
    const float* ema_sq   = (const float*)d_in[2];
    const float* ema_out  = (const float*)d_in[3];
    const float* lt       = (const float*)d_in[4];
    const float* lbu      = (const float*)d_in[5];
    const float* lg       = (const float*)d_in[6];
    const float* lbf      = (const float*)d_in[7];
    float* out = (float*)d_out;

    int rows = in_sizes[0] / DD;
    if (rows < 1) rows = 1;

    prep_kernel<<<1, NT>>>(ema_mean, ema_sq, ema_out, lt, lbu, lg, lbf);
    gelu_gate_kernel<<<rows, NT>>>(x, ema_out, out);
}